// round 11
// baseline (speedup 1.0000x reference)
#include <cuda_runtime.h>
#include <cuda_bf16.h>
#include <cstdint>

// ---------------- Problem constants ----------------
#define B_ 4
#define T_ 1024
#define E_ 1024
#define H_ 16
#define D_ 64
#define M_ 4096
#define SCALE_ 0.125f
#define WEPS_ 1e-5f
#define NEGINF_ -1e30f
#define ME_ (M_*E_)
#define EE_ (E_*E_)

// ---------------- Scratch (__device__ globals) ----------
__device__ __align__(16) __nv_bfloat16 g_ahi[3*ME_];   // act hi: slots q,k,v (slot0 reused by flash out)
__device__ __align__(16) __nv_bfloat16 g_alo[3*ME_];
__device__ __align__(16) __nv_bfloat16 g_bhi[4*EE_];   // weights hi: Wq,Wk,Wv,Wo
__device__ __align__(16) __nv_bfloat16 g_blo[4*EE_];
// projected Q/K: [head][t][64]; V transposed: [head][d][t]
__device__ __align__(16) __nv_bfloat16 g_qhh[64*T_*D_];
__device__ __align__(16) __nv_bfloat16 g_qhl[64*T_*D_];
__device__ __align__(16) __nv_bfloat16 g_khh[64*T_*D_];
__device__ __align__(16) __nv_bfloat16 g_khl[64*T_*D_];
__device__ __align__(16) __nv_bfloat16 g_vhh[64*D_*T_];
__device__ __align__(16) __nv_bfloat16 g_vhl[64*D_*T_];

__device__ __forceinline__ uint32_t smem_u32(const void* p) {
    uint32_t a;
    asm("{ .reg .u64 t; cvta.to.shared.u64 t, %1; cvt.u32.u64 %0, t; }" : "=r"(a) : "l"(p));
    return a;
}
__device__ __forceinline__ void cp16(uint32_t dst, const void* src) {
    asm volatile("cp.async.ca.shared.global [%0], [%1], 16;" :: "r"(dst), "l"(src));
}
#define CP_COMMIT() asm volatile("cp.async.commit_group;" ::: "memory")

__device__ __forceinline__ void ldsm_x4(uint32_t* r, uint32_t addr) {
    asm volatile("ldmatrix.sync.aligned.m8n8.x4.shared.b16 {%0,%1,%2,%3}, [%4];"
        : "=r"(r[0]), "=r"(r[1]), "=r"(r[2]), "=r"(r[3]) : "r"(addr));
}
__device__ __forceinline__ void mma16816(float* c, const uint32_t* a, uint32_t b0, uint32_t b1) {
    asm volatile("mma.sync.aligned.m16n8k16.row.col.f32.bf16.bf16.f32 "
        "{%0,%1,%2,%3}, {%4,%5,%6,%7}, {%8,%9}, {%0,%1,%2,%3};"
        : "+f"(c[0]), "+f"(c[1]), "+f"(c[2]), "+f"(c[3])
        : "r"(a[0]), "r"(a[1]), "r"(a[2]), "r"(a[3]), "r"(b0), "r"(b1));
}
__device__ __forceinline__ uint32_t pack_bf2(float lo, float hi) {
    __nv_bfloat162 t(__float2bfloat16(lo), __float2bfloat16(hi));
    return *(uint32_t*)&t;
}

// ---------------------------------------------------------------------------
// Fused splits
// ---------------------------------------------------------------------------
__global__ void split_acts(const float* __restrict__ q, const float* __restrict__ k,
                           const float* __restrict__ v)
{
    const int n4 = ME_ / 4;
    int i = blockIdx.x * blockDim.x + threadIdx.x;
    if (i >= 3 * n4) return;
    int slot = i / n4, off = i - slot * n4;
    const float* src = (slot == 0) ? q : (slot == 1) ? k : v;
    float4 x = ((const float4*)src)[off];
    __nv_bfloat16 h0 = __float2bfloat16(x.x), h1 = __float2bfloat16(x.y);
    __nv_bfloat16 h2 = __float2bfloat16(x.z), h3 = __float2bfloat16(x.w);
    __nv_bfloat16 l0 = __float2bfloat16(x.x - __bfloat162float(h0));
    __nv_bfloat16 l1 = __float2bfloat16(x.y - __bfloat162float(h1));
    __nv_bfloat16 l2 = __float2bfloat16(x.z - __bfloat162float(h2));
    __nv_bfloat16 l3 = __float2bfloat16(x.w - __bfloat162float(h3));
    size_t o2 = ((size_t)slot * ME_ + (size_t)off * 4) >> 1;
    ((__nv_bfloat162*)g_ahi)[o2+0] = __nv_bfloat162(h0, h1);
    ((__nv_bfloat162*)g_ahi)[o2+1] = __nv_bfloat162(h2, h3);
    ((__nv_bfloat162*)g_alo)[o2+0] = __nv_bfloat162(l0, l1);
    ((__nv_bfloat162*)g_alo)[o2+1] = __nv_bfloat162(l2, l3);
}

__global__ void split_ws(const float* __restrict__ w0, const float* __restrict__ w1,
                         const float* __restrict__ w2, const float* __restrict__ w3)
{
    const int n4 = EE_ / 4;
    int i = blockIdx.x * blockDim.x + threadIdx.x;
    if (i >= 4 * n4) return;
    int slot = i / n4, off = i - slot * n4;
    const float* src = (slot == 0) ? w0 : (slot == 1) ? w1 : (slot == 2) ? w2 : w3;
    float4 x = ((const float4*)src)[off];
    __nv_bfloat16 h0 = __float2bfloat16(x.x), h1 = __float2bfloat16(x.y);
    __nv_bfloat16 h2 = __float2bfloat16(x.z), h3 = __float2bfloat16(x.w);
    __nv_bfloat16 l0 = __float2bfloat16(x.x - __bfloat162float(h0));
    __nv_bfloat16 l1 = __float2bfloat16(x.y - __bfloat162float(h1));
    __nv_bfloat16 l2 = __float2bfloat16(x.z - __bfloat162float(h2));
    __nv_bfloat16 l3 = __float2bfloat16(x.w - __bfloat162float(h3));
    size_t o2 = ((size_t)slot * EE_ + (size_t)off * 4) >> 1;
    ((__nv_bfloat162*)g_bhi)[o2+0] = __nv_bfloat162(h0, h1);
    ((__nv_bfloat162*)g_bhi)[o2+1] = __nv_bfloat162(h2, h3);
    ((__nv_bfloat162*)g_blo)[o2+0] = __nv_bfloat162(l0, l1);
    ((__nv_bfloat162*)g_blo)[o2+1] = __nv_bfloat162(l2, l3);
}

// ---------------------------------------------------------------------------
// HMMA GEMM, 4-stage cp.async pipeline. C = A·B^T over K'=3072 (hi/lo 3-term).
// CTA 128x128, 8 warps. base_mode 0: mode=blockIdx.z (0=Q,1=K,2=V); base_mode 3: out.
// Dynamic smem: A[4][128][40] @0, B[4][128][40] @40960. Total 81920 B.
// ---------------------------------------------------------------------------
#define GSM_B_OFF 40960
#define GSM_TOTAL 81920
#define NCHUNK 96

__global__ void __launch_bounds__(256, 2) gemm_mma(
    const float* __restrict__ bias0, const float* __restrict__ bias1,
    const float* __restrict__ bias2, float* __restrict__ out, int base_mode)
{
    extern __shared__ char gsm[];
    const int tid = threadIdx.x;
    const int lane = tid & 31;
    const int wid = tid >> 5;
    const int wm = wid & 3;
    const int wn = wid >> 2;
    const int m0 = blockIdx.y * 128;
    const int n0 = blockIdx.x * 128;
    const int mode = (base_mode == 3) ? 3 : (int)blockIdx.z;
    const int aslot = (mode == 3) ? 0 : mode;
    const int wslot = (mode == 3) ? 3 : mode;
    const float* bias = (mode == 1) ? bias1 : (mode == 2) ? bias2 : bias0;

    const __nv_bfloat16* Ahi = g_ahi + (size_t)aslot * ME_;
    const __nv_bfloat16* Alo = g_alo + (size_t)aslot * ME_;
    const __nv_bfloat16* Bhi = g_bhi + (size_t)wslot * EE_;
    const __nv_bfloat16* Blo = g_blo + (size_t)wslot * EE_;

    const uint32_t sAu = smem_u32(gsm);
    const uint32_t sBu = sAu + GSM_B_OFF;

    float acc[2][8][4];
    #pragma unroll
    for (int i = 0; i < 2; i++)
        #pragma unroll
        for (int j = 0; j < 8; j++)
            #pragma unroll
            for (int q = 0; q < 4; q++) acc[i][j][q] = 0.0f;

    const int lr = tid >> 2;
    const int lk = (tid & 3) * 8;

    auto issue = [&](int c, int s) {
        const __nv_bfloat16* Ap = (c < 32 || c >= 64) ? Ahi : Alo;
        const __nv_bfloat16* Bp = (c < 64) ? Bhi : Blo;
        const int koff = (c & 31) * 32;
        #pragma unroll
        for (int i = 0; i < 2; i++) {
            int row = lr + i * 64;
            uint32_t off = (uint32_t)(((s * 128 + row) * 40 + lk) * 2);
            cp16(sAu + off, Ap + (size_t)(m0 + row) * E_ + koff + lk);
            cp16(sBu + off, Bp + (size_t)(n0 + row) * E_ + koff + lk);
        }
    };

    issue(0, 0); CP_COMMIT();
    issue(1, 1); CP_COMMIT();
    issue(2, 2); CP_COMMIT();

    for (int c = 0; c < NCHUNK; c++) {
        const int s = c & 3;
        if (c <= NCHUNK - 3)      asm volatile("cp.async.wait_group 2;" ::: "memory");
        else if (c == NCHUNK - 2) asm volatile("cp.async.wait_group 1;" ::: "memory");
        else                      asm volatile("cp.async.wait_group 0;" ::: "memory");
        __syncthreads();
        if (c + 3 < NCHUNK) { issue(c + 3, (c + 3) & 3); CP_COMMIT(); }

        #pragma unroll
        for (int ks = 0; ks < 2; ks++) {
            uint32_t a[2][4];
            #pragma unroll
            for (int mf = 0; mf < 2; mf++) {
                int row = wm * 32 + mf * 16 + (lane & 15);
                int col = ks * 16 + (lane >> 4) * 8;
                ldsm_x4(a[mf], sAu + (uint32_t)(((s * 128 + row) * 40 + col) * 2));
            }
            uint32_t b[4][4];
            #pragma unroll
            for (int nf2 = 0; nf2 < 4; nf2++) {
                int row = wn * 64 + nf2 * 16 + (lane & 7) + (lane >> 4) * 8;
                int col = ks * 16 + ((lane >> 3) & 1) * 8;
                ldsm_x4(b[nf2], sBu + (uint32_t)(((s * 128 + row) * 40 + col) * 2));
            }
            #pragma unroll
            for (int mf = 0; mf < 2; mf++)
                #pragma unroll
                for (int nf2 = 0; nf2 < 4; nf2++) {
                    mma16816(acc[mf][nf2 * 2 + 0], a[mf], b[nf2][0], b[nf2][1]);
                    mma16816(acc[mf][nf2 * 2 + 1], a[mf], b[nf2][2], b[nf2][3]);
                }
        }
    }

    const int gid = lane >> 2;
    const int tig = lane & 3;
    #pragma unroll
    for (int mf = 0; mf < 2; mf++) {
        #pragma unroll
        for (int nf = 0; nf < 8; nf++) {
            int row = m0 + wm * 32 + mf * 16 + gid;
            int col = n0 + wn * 64 + nf * 8 + tig * 2;
            float b0 = bias[col], b1 = bias[col + 1];
            float v00 = acc[mf][nf][0] + b0, v01 = acc[mf][nf][1] + b1;
            float v10 = acc[mf][nf][2] + b0, v11 = acc[mf][nf][3] + b1;
            if (mode == 3) {
                *(float2*)&out[(size_t)row * E_ + col] = make_float2(v00, v01);
                *(float2*)&out[(size_t)(row + 8) * E_ + col] = make_float2(v10, v11);
            } else {
                int h = (row >> 10) * 16 + (col >> 6);
                int t0 = row & 1023, d = col & 63;
                __nv_bfloat16 h00 = __float2bfloat16(v00), h01 = __float2bfloat16(v01);
                __nv_bfloat16 h10 = __float2bfloat16(v10), h11 = __float2bfloat16(v11);
                __nv_bfloat16 l00 = __float2bfloat16(v00 - __bfloat162float(h00));
                __nv_bfloat16 l01 = __float2bfloat16(v01 - __bfloat162float(h01));
                __nv_bfloat16 l10 = __float2bfloat16(v10 - __bfloat162float(h10));
                __nv_bfloat16 l11 = __float2bfloat16(v11 - __bfloat162float(h11));
                if (mode == 2) {
                    size_t base = ((size_t)h * 64 + d) * 1024;
                    g_vhh[base + t0] = h00;          g_vhh[base + 1024 + t0] = h01;
                    g_vhh[base + t0 + 8] = h10;      g_vhh[base + 1024 + t0 + 8] = h11;
                    g_vhl[base + t0] = l00;          g_vhl[base + 1024 + t0] = l01;
                    g_vhl[base + t0 + 8] = l10;      g_vhl[base + 1024 + t0 + 8] = l11;
                } else {
                    __nv_bfloat16* Hh = (mode == 0) ? g_qhh : g_khh;
                    __nv_bfloat16* Hl = (mode == 0) ? g_qhl : g_khl;
                    size_t i0 = ((size_t)h * 1024 + t0) * 64 + d;
                    size_t i1 = ((size_t)h * 1024 + t0 + 8) * 64 + d;
                    *(__nv_bfloat162*)(Hh + i0) = __nv_bfloat162(h00, h01);
                    *(__nv_bfloat162*)(Hl + i0) = __nv_bfloat162(l00, l01);
                    *(__nv_bfloat162*)(Hh + i1) = __nv_bfloat162(h10, h11);
                    *(__nv_bfloat162*)(Hl + i1) = __nv_bfloat162(l10, l11);
                }
            }
        }
    }
}

// ---------------------------------------------------------------------------
// Fused flash attention. Output written as hi/lo bf16 split directly into
// flat [M,E] layout in g_ahi/g_alo slot 0 (A operand of the output GEMM).
// ---------------------------------------------------------------------------
#define KSTR 72
#define VSTR 136
#define KHI_OFF 0
#define KLO_OFF 18432
#define VHI_OFF 36864
#define VLO_OFF 54272
#define STAGE_SZ 71680
#define SW_OFF  143360
#define FLASH_SMEM (SW_OFF + 1024)

__global__ void __launch_bounds__(256) flash_kernel(const float* __restrict__ weights)
{
    extern __shared__ char sm[];
    const int tid = threadIdx.x, lane = tid & 31, wid = tid >> 5;
    const int head = blockIdx.y, m0 = blockIdx.x * 128;
    const int batch = head >> 4, hidx = head & 15;
    const uint32_t smb = smem_u32(sm);

    #pragma unroll
    for (int i = 0; i < 4; i++) {
        int task = tid + i * 256;
        int r = task >> 3, ch = task & 7;
        size_t src = ((size_t)head * 1024 + m0 + r) * 64 + ch * 8;
        cp16(smb + KHI_OFF + r * 144 + ch * 16, g_qhh + src);
        cp16(smb + KLO_OFF + r * 144 + ch * 16, g_qhl + src);
    }
    CP_COMMIT();
    asm volatile("cp.async.wait_group 0;" ::: "memory");
    __syncthreads();

    uint32_t qhi[4][4], qlo[4][4];
    {
        int row = wid * 16 + (lane & 15);
        #pragma unroll
        for (int kc = 0; kc < 4; kc++) {
            int col = kc * 16 + (lane >> 4) * 8;
            ldsm_x4(qhi[kc], smb + KHI_OFF + (uint32_t)((row * KSTR + col) * 2));
            ldsm_x4(qlo[kc], smb + KLO_OFF + (uint32_t)((row * KSTR + col) * 2));
        }
    }
    __syncthreads();

    auto issue = [&](int kt, int s) {
        uint32_t base = smb + s * STAGE_SZ;
        int k0 = kt * 128;
        #pragma unroll
        for (int i = 0; i < 4; i++) {
            int task = tid + i * 256;
            int r = task >> 3, ch = task & 7;
            size_t src = ((size_t)head * 1024 + k0 + r) * 64 + ch * 8;
            cp16(base + KHI_OFF + r * 144 + ch * 16, g_khh + src);
            cp16(base + KLO_OFF + r * 144 + ch * 16, g_khl + src);
        }
        #pragma unroll
        for (int i = 0; i < 4; i++) {
            int task = tid + i * 256;
            int r = task >> 4, ch = task & 15;
            size_t src = ((size_t)head * 64 + r) * 1024 + k0 + ch * 8;
            cp16(base + VHI_OFF + r * 272 + ch * 16, g_vhh + src);
            cp16(base + VLO_OFF + r * 272 + ch * 16, g_vhl + src);
        }
        if (tid < 128) {
            float w = weights[(size_t)batch * 1024 + k0 + tid];
            float scl = (w < WEPS_) ? -1.0f : SCALE_ * w * w;
            *(float*)(sm + SW_OFF + s * 512 + tid * 4) = scl;
        }
    };

    const int gid = lane >> 2, tig = lane & 3;
    const int brow = (lane & 7) + ((lane >> 4) << 3);
    const int bcol = ((lane >> 3) & 1) * 8;

    float m_st[2] = {NEGINF_, NEGINF_};
    float l_st[2] = {0.0f, 0.0f};
    float oacc[8][4];
    #pragma unroll
    for (int i = 0; i < 8; i++)
        #pragma unroll
        for (int j = 0; j < 4; j++) oacc[i][j] = 0.0f;

    issue(0, 0);
    CP_COMMIT();

    for (int kt = 0; kt < 8; kt++) {
        const int s = kt & 1;
        if (kt + 1 < 8) {
            issue(kt + 1, s ^ 1);
            CP_COMMIT();
            asm volatile("cp.async.wait_group 1;" ::: "memory");
        } else {
            asm volatile("cp.async.wait_group 0;" ::: "memory");
        }
        __syncthreads();

        const uint32_t kb = smb + s * STAGE_SZ;
        float sacc[16][4];
        #pragma unroll
        for (int nb = 0; nb < 16; nb++)
            #pragma unroll
            for (int q = 0; q < 4; q++) sacc[nb][q] = 0.0f;

        #pragma unroll
        for (int kc = 0; kc < 4; kc++) {
            #pragma unroll
            for (int nf2 = 0; nf2 < 8; nf2++) {
                uint32_t b[4];
                int row = nf2 * 16 + brow;
                int col = kc * 16 + bcol;
                ldsm_x4(b, kb + KHI_OFF + (uint32_t)((row * KSTR + col) * 2));
                mma16816(sacc[2*nf2],   qhi[kc], b[0], b[1]);
                mma16816(sacc[2*nf2+1], qhi[kc], b[2], b[3]);
                mma16816(sacc[2*nf2],   qlo[kc], b[0], b[1]);
                mma16816(sacc[2*nf2+1], qlo[kc], b[2], b[3]);
                ldsm_x4(b, kb + KLO_OFF + (uint32_t)((row * KSTR + col) * 2));
                mma16816(sacc[2*nf2],   qhi[kc], b[0], b[1]);
                mma16816(sacc[2*nf2+1], qhi[kc], b[2], b[3]);
            }
        }

        const float* sw = (const float*)(sm + SW_OFF + s * 512);
        float mx0 = NEGINF_, mx1 = NEGINF_;
        #pragma unroll
        for (int nb = 0; nb < 16; nb++) {
            float sc0 = sw[nb * 8 + tig * 2];
            float sc1 = sw[nb * 8 + tig * 2 + 1];
            float v0 = (sc0 < 0.f) ? NEGINF_ : sacc[nb][0] * sc0;
            float v1 = (sc1 < 0.f) ? NEGINF_ : sacc[nb][1] * sc1;
            float v2 = (sc0 < 0.f) ? NEGINF_ : sacc[nb][2] * sc0;
            float v3 = (sc1 < 0.f) ? NEGINF_ : sacc[nb][3] * sc1;
            sacc[nb][0] = v0; sacc[nb][1] = v1; sacc[nb][2] = v2; sacc[nb][3] = v3;
            mx0 = fmaxf(mx0, fmaxf(v0, v1));
            mx1 = fmaxf(mx1, fmaxf(v2, v3));
        }
        mx0 = fmaxf(mx0, __shfl_xor_sync(0xffffffffu, mx0, 1));
        mx0 = fmaxf(mx0, __shfl_xor_sync(0xffffffffu, mx0, 2));
        mx1 = fmaxf(mx1, __shfl_xor_sync(0xffffffffu, mx1, 1));
        mx1 = fmaxf(mx1, __shfl_xor_sync(0xffffffffu, mx1, 2));

        float mn0 = fmaxf(m_st[0], mx0), mn1 = fmaxf(m_st[1], mx1);
        float al0 = (m_st[0] == mn0) ? 1.0f : __expf(m_st[0] - mn0);
        float al1 = (m_st[1] == mn1) ? 1.0f : __expf(m_st[1] - mn1);
        float ms0 = (mn0 <= -1e29f) ? 0.0f : mn0;
        float ms1 = (mn1 <= -1e29f) ? 0.0f : mn1;

        float sum0 = 0.f, sum1 = 0.f;
        #pragma unroll
        for (int nb = 0; nb < 16; nb++) {
            float p0 = __expf(fmaxf(sacc[nb][0] - ms0, -80.f));
            float p1 = __expf(fmaxf(sacc[nb][1] - ms0, -80.f));
            float p2 = __expf(fmaxf(sacc[nb][2] - ms1, -80.f));
            float p3 = __expf(fmaxf(sacc[nb][3] - ms1, -80.f));
            sacc[nb][0] = p0; sacc[nb][1] = p1; sacc[nb][2] = p2; sacc[nb][3] = p3;
            sum0 += p0 + p1; sum1 += p2 + p3;
        }
        sum0 += __shfl_xor_sync(0xffffffffu, sum0, 1);
        sum0 += __shfl_xor_sync(0xffffffffu, sum0, 2);
        sum1 += __shfl_xor_sync(0xffffffffu, sum1, 1);
        sum1 += __shfl_xor_sync(0xffffffffu, sum1, 2);

        l_st[0] = l_st[0] * al0 + sum0;
        l_st[1] = l_st[1] * al1 + sum1;
        m_st[0] = mn0; m_st[1] = mn1;

        #pragma unroll
        for (int nb = 0; nb < 8; nb++) {
            oacc[nb][0] *= al0; oacc[nb][1] *= al0;
            oacc[nb][2] *= al1; oacc[nb][3] *= al1;
        }

        #pragma unroll
        for (int kc = 0; kc < 8; kc++) {
            uint32_t aphi[4], aplo[4];
            #pragma unroll
            for (int half = 0; half < 2; half++) {
                float p0 = sacc[2*kc + half][0], p1 = sacc[2*kc + half][1];
                float p2 = sacc[2*kc + half][2], p3 = sacc[2*kc + half][3];
                __nv_bfloat16 h0 = __float2bfloat16(p0), h1 = __float2bfloat16(p1);
                __nv_bfloat16 h2 = __float2bfloat16(p2), h3 = __float2bfloat16(p3);
                float r0 = p0 - __bfloat162float(h0), r1 = p1 - __bfloat162float(h1);
                float r2 = p2 - __bfloat162float(h2), r3 = p3 - __bfloat162float(h3);
                __nv_bfloat162 th0(h0, h1), th1(h2, h3);
                aphi[2*half + 0] = *(uint32_t*)&th0;
                aphi[2*half + 1] = *(uint32_t*)&th1;
                aplo[2*half + 0] = pack_bf2(r0, r1);
                aplo[2*half + 1] = pack_bf2(r2, r3);
            }
            #pragma unroll
            for (int nf2 = 0; nf2 < 4; nf2++) {
                uint32_t b[4];
                int row = nf2 * 16 + brow;
                int col = kc * 16 + bcol;
                ldsm_x4(b, kb + VHI_OFF + (uint32_t)((row * VSTR + col) * 2));
                mma16816(oacc[2*nf2],   aphi, b[0], b[1]);
                mma16816(oacc[2*nf2+1], aphi, b[2], b[3]);
                mma16816(oacc[2*nf2],   aplo, b[0], b[1]);
                mma16816(oacc[2*nf2+1], aplo, b[2], b[3]);
                ldsm_x4(b, kb + VLO_OFF + (uint32_t)((row * VSTR + col) * 2));
                mma16816(oacc[2*nf2],   aphi, b[0], b[1]);
                mma16816(oacc[2*nf2+1], aphi, b[2], b[3]);
            }
        }
        __syncthreads();
    }

    // ---- normalize & write hi/lo split directly to flat [M,E] slot 0
    float inv0 = 1.0f / l_st[0], inv1 = 1.0f / l_st[1];
    int t0 = m0 + wid * 16 + gid;
    size_t mf0 = (size_t)(batch * 1024 + t0) * E_ + hidx * 64;
    size_t mf1 = mf0 + 8 * E_;
    #pragma unroll
    for (int nb = 0; nb < 8; nb++) {
        int col = nb * 8 + tig * 2;
        float v0 = oacc[nb][0] * inv0, v1 = oacc[nb][1] * inv0;
        float v2 = oacc[nb][2] * inv1, v3 = oacc[nb][3] * inv1;
        __nv_bfloat16 h0 = __float2bfloat16(v0), h1 = __float2bfloat16(v1);
        __nv_bfloat16 h2 = __float2bfloat16(v2), h3 = __float2bfloat16(v3);
        __nv_bfloat16 l0 = __float2bfloat16(v0 - __bfloat162float(h0));
        __nv_bfloat16 l1 = __float2bfloat16(v1 - __bfloat162float(h1));
        __nv_bfloat16 l2 = __float2bfloat16(v2 - __bfloat162float(h2));
        __nv_bfloat16 l3 = __float2bfloat16(v3 - __bfloat162float(h3));
        *(__nv_bfloat162*)(g_ahi + mf0 + col) = __nv_bfloat162(h0, h1);
        *(__nv_bfloat162*)(g_alo + mf0 + col) = __nv_bfloat162(l0, l1);
        *(__nv_bfloat162*)(g_ahi + mf1 + col) = __nv_bfloat162(h2, h3);
        *(__nv_bfloat162*)(g_alo + mf1 + col) = __nv_bfloat162(l2, l3);
    }
}

// ---------------------------------------------------------------------------
extern "C" void kernel_launch(void* const* d_in, const int* in_sizes, int n_in,
                              void* d_out, int out_size)
{
    const float* q       = (const float*)d_in[0];
    const float* k       = (const float*)d_in[1];
    const float* v       = (const float*)d_in[2];
    const float* weights = (const float*)d_in[3];
    const float* Wq      = (const float*)d_in[4];
    const float* bq      = (const float*)d_in[5];
    const float* Wk      = (const float*)d_in[6];
    const float* bk      = (const float*)d_in[7];
    const float* Wv      = (const float*)d_in[8];
    const float* bv      = (const float*)d_in[9];
    const float* Wo      = (const float*)d_in[10];
    const float* bo      = (const float*)d_in[11];
    float* out = (float*)d_out;

    dim3 blk(256);

    static bool attr_set = false;
    if (!attr_set) {
        cudaFuncSetAttribute(flash_kernel, cudaFuncAttributeMaxDynamicSharedMemorySize, FLASH_SMEM);
        cudaFuncSetAttribute(gemm_mma, cudaFuncAttributeMaxDynamicSharedMemorySize, GSM_TOTAL);
        attr_set = true;
    }

    split_ws<<<(4 * EE_ / 4 + 255) / 256, blk>>>(Wq, Wk, Wv, Wo);
    split_acts<<<(3 * ME_ / 4 + 255) / 256, blk>>>(q, k, v);
    gemm_mma<<<dim3(8, 32, 3), blk, GSM_TOTAL>>>(bq, bk, bv, nullptr, 0);
    flash_kernel<<<dim3(8, 64), blk, FLASH_SMEM>>>(weights);
    gemm_mma<<<dim3(8, 32, 1), blk, GSM_TOTAL>>>(bo, bo, bo, out, 3);
}

// round 12
// speedup vs baseline: 1.5609x; 1.5609x over previous
#include <cuda_runtime.h>
#include <cuda_bf16.h>
#include <cstdint>

// ---------------- Problem constants ----------------
#define B_ 4
#define T_ 1024
#define E_ 1024
#define H_ 16
#define D_ 64
#define M_ 4096
#define SCALE_ 0.125f
#define WEPS_ 1e-5f
#define NEGINF_ -1e30f
#define ME_ (M_*E_)
#define EE_ (E_*E_)

// ---------------- Scratch (__device__ globals) ----------
__device__ __align__(16) __nv_bfloat16 g_ahi[3*ME_];   // act hi: slots q,k,v (slot0 reused by flash out)
__device__ __align__(16) __nv_bfloat16 g_alo[3*ME_];
__device__ __align__(16) __nv_bfloat16 g_bhi[4*EE_];   // weights hi: Wq,Wk,Wv,Wo
__device__ __align__(16) __nv_bfloat16 g_blo[4*EE_];
// projected Q/K: [head][t][64]; V transposed: [head][d][t]
__device__ __align__(16) __nv_bfloat16 g_qhh[64*T_*D_];
__device__ __align__(16) __nv_bfloat16 g_qhl[64*T_*D_];
__device__ __align__(16) __nv_bfloat16 g_khh[64*T_*D_];
__device__ __align__(16) __nv_bfloat16 g_khl[64*T_*D_];
__device__ __align__(16) __nv_bfloat16 g_vhh[64*D_*T_];
__device__ __align__(16) __nv_bfloat16 g_vhl[64*D_*T_];

__device__ __forceinline__ uint32_t smem_u32(const void* p) {
    uint32_t a;
    asm("{ .reg .u64 t; cvta.to.shared.u64 t, %1; cvt.u32.u64 %0, t; }" : "=r"(a) : "l"(p));
    return a;
}
__device__ __forceinline__ void cp16(uint32_t dst, const void* src) {
    asm volatile("cp.async.ca.shared.global [%0], [%1], 16;" :: "r"(dst), "l"(src));
}
#define CP_COMMIT() asm volatile("cp.async.commit_group;" ::: "memory")

__device__ __forceinline__ void ldsm_x4(uint32_t* r, uint32_t addr) {
    asm volatile("ldmatrix.sync.aligned.m8n8.x4.shared.b16 {%0,%1,%2,%3}, [%4];"
        : "=r"(r[0]), "=r"(r[1]), "=r"(r[2]), "=r"(r[3]) : "r"(addr));
}
__device__ __forceinline__ void mma16816(float* c, const uint32_t* a, uint32_t b0, uint32_t b1) {
    asm volatile("mma.sync.aligned.m16n8k16.row.col.f32.bf16.bf16.f32 "
        "{%0,%1,%2,%3}, {%4,%5,%6,%7}, {%8,%9}, {%0,%1,%2,%3};"
        : "+f"(c[0]), "+f"(c[1]), "+f"(c[2]), "+f"(c[3])
        : "r"(a[0]), "r"(a[1]), "r"(a[2]), "r"(a[3]), "r"(b0), "r"(b1));
}
__device__ __forceinline__ uint32_t pack_bf2(float lo, float hi) {
    __nv_bfloat162 t(__float2bfloat16(lo), __float2bfloat16(hi));
    return *(uint32_t*)&t;
}

// ---------------------------------------------------------------------------
// Fused splits
// ---------------------------------------------------------------------------
__global__ void split_acts(const float* __restrict__ q, const float* __restrict__ k,
                           const float* __restrict__ v)
{
    const int n4 = ME_ / 4;
    int i = blockIdx.x * blockDim.x + threadIdx.x;
    if (i >= 3 * n4) return;
    int slot = i / n4, off = i - slot * n4;
    const float* src = (slot == 0) ? q : (slot == 1) ? k : v;
    float4 x = ((const float4*)src)[off];
    __nv_bfloat16 h0 = __float2bfloat16(x.x), h1 = __float2bfloat16(x.y);
    __nv_bfloat16 h2 = __float2bfloat16(x.z), h3 = __float2bfloat16(x.w);
    __nv_bfloat16 l0 = __float2bfloat16(x.x - __bfloat162float(h0));
    __nv_bfloat16 l1 = __float2bfloat16(x.y - __bfloat162float(h1));
    __nv_bfloat16 l2 = __float2bfloat16(x.z - __bfloat162float(h2));
    __nv_bfloat16 l3 = __float2bfloat16(x.w - __bfloat162float(h3));
    size_t o2 = ((size_t)slot * ME_ + (size_t)off * 4) >> 1;
    ((__nv_bfloat162*)g_ahi)[o2+0] = __nv_bfloat162(h0, h1);
    ((__nv_bfloat162*)g_ahi)[o2+1] = __nv_bfloat162(h2, h3);
    ((__nv_bfloat162*)g_alo)[o2+0] = __nv_bfloat162(l0, l1);
    ((__nv_bfloat162*)g_alo)[o2+1] = __nv_bfloat162(l2, l3);
}

__global__ void split_ws(const float* __restrict__ w0, const float* __restrict__ w1,
                         const float* __restrict__ w2, const float* __restrict__ w3)
{
    const int n4 = EE_ / 4;
    int i = blockIdx.x * blockDim.x + threadIdx.x;
    if (i >= 4 * n4) return;
    int slot = i / n4, off = i - slot * n4;
    const float* src = (slot == 0) ? w0 : (slot == 1) ? w1 : (slot == 2) ? w2 : w3;
    float4 x = ((const float4*)src)[off];
    __nv_bfloat16 h0 = __float2bfloat16(x.x), h1 = __float2bfloat16(x.y);
    __nv_bfloat16 h2 = __float2bfloat16(x.z), h3 = __float2bfloat16(x.w);
    __nv_bfloat16 l0 = __float2bfloat16(x.x - __bfloat162float(h0));
    __nv_bfloat16 l1 = __float2bfloat16(x.y - __bfloat162float(h1));
    __nv_bfloat16 l2 = __float2bfloat16(x.z - __bfloat162float(h2));
    __nv_bfloat16 l3 = __float2bfloat16(x.w - __bfloat162float(h3));
    size_t o2 = ((size_t)slot * EE_ + (size_t)off * 4) >> 1;
    ((__nv_bfloat162*)g_bhi)[o2+0] = __nv_bfloat162(h0, h1);
    ((__nv_bfloat162*)g_bhi)[o2+1] = __nv_bfloat162(h2, h3);
    ((__nv_bfloat162*)g_blo)[o2+0] = __nv_bfloat162(l0, l1);
    ((__nv_bfloat162*)g_blo)[o2+1] = __nv_bfloat162(l2, l3);
}

// ---------------------------------------------------------------------------
// HMMA GEMM, 4-stage cp.async pipeline, 1 CTA/SM (no reg cap -> no spills).
// C = A·B^T over K'=3072 (hi/lo 3-term). CTA 128x128, 8 warps.
// base_mode 0: mode=blockIdx.z (0=Q,1=K,2=V); base_mode 3: fp32 out + bias.
// Dynamic smem: A[4][128][40] @0, B[4][128][40] @40960. Total 81920 B.
// ---------------------------------------------------------------------------
#define GSM_B_OFF 40960
#define GSM_TOTAL 81920
#define NCHUNK 96

__global__ void __launch_bounds__(256) gemm_mma(
    const float* __restrict__ bias0, const float* __restrict__ bias1,
    const float* __restrict__ bias2, float* __restrict__ out, int base_mode)
{
    extern __shared__ char gsm[];
    const int tid = threadIdx.x;
    const int lane = tid & 31;
    const int wid = tid >> 5;
    const int wm = wid & 3;
    const int wn = wid >> 2;
    const int m0 = blockIdx.y * 128;
    const int n0 = blockIdx.x * 128;
    const int mode = (base_mode == 3) ? 3 : (int)blockIdx.z;
    const int aslot = (mode == 3) ? 0 : mode;
    const int wslot = (mode == 3) ? 3 : mode;
    const float* bias = (mode == 1) ? bias1 : (mode == 2) ? bias2 : bias0;

    const __nv_bfloat16* Ahi = g_ahi + (size_t)aslot * ME_;
    const __nv_bfloat16* Alo = g_alo + (size_t)aslot * ME_;
    const __nv_bfloat16* Bhi = g_bhi + (size_t)wslot * EE_;
    const __nv_bfloat16* Blo = g_blo + (size_t)wslot * EE_;

    const uint32_t sAu = smem_u32(gsm);
    const uint32_t sBu = sAu + GSM_B_OFF;

    float acc[2][8][4];
    #pragma unroll
    for (int i = 0; i < 2; i++)
        #pragma unroll
        for (int j = 0; j < 8; j++)
            #pragma unroll
            for (int q = 0; q < 4; q++) acc[i][j][q] = 0.0f;

    const int lr = tid >> 2;
    const int lk = (tid & 3) * 8;

    auto issue = [&](int c, int s) {
        const __nv_bfloat16* Ap = (c < 32 || c >= 64) ? Ahi : Alo;
        const __nv_bfloat16* Bp = (c < 64) ? Bhi : Blo;
        const int koff = (c & 31) * 32;
        #pragma unroll
        for (int i = 0; i < 2; i++) {
            int row = lr + i * 64;
            uint32_t off = (uint32_t)(((s * 128 + row) * 40 + lk) * 2);
            cp16(sAu + off, Ap + (size_t)(m0 + row) * E_ + koff + lk);
            cp16(sBu + off, Bp + (size_t)(n0 + row) * E_ + koff + lk);
        }
    };

    issue(0, 0); CP_COMMIT();
    issue(1, 1); CP_COMMIT();
    issue(2, 2); CP_COMMIT();

    for (int c = 0; c < NCHUNK; c++) {
        const int s = c & 3;
        if (c <= NCHUNK - 3)      asm volatile("cp.async.wait_group 2;" ::: "memory");
        else if (c == NCHUNK - 2) asm volatile("cp.async.wait_group 1;" ::: "memory");
        else                      asm volatile("cp.async.wait_group 0;" ::: "memory");
        __syncthreads();
        if (c + 3 < NCHUNK) { issue(c + 3, (c + 3) & 3); CP_COMMIT(); }

        #pragma unroll
        for (int ks = 0; ks < 2; ks++) {
            uint32_t a[2][4];
            #pragma unroll
            for (int mf = 0; mf < 2; mf++) {
                int row = wm * 32 + mf * 16 + (lane & 15);
                int col = ks * 16 + (lane >> 4) * 8;
                ldsm_x4(a[mf], sAu + (uint32_t)(((s * 128 + row) * 40 + col) * 2));
            }
            uint32_t b[4][4];
            #pragma unroll
            for (int nf2 = 0; nf2 < 4; nf2++) {
                int row = wn * 64 + nf2 * 16 + (lane & 7) + (lane >> 4) * 8;
                int col = ks * 16 + ((lane >> 3) & 1) * 8;
                ldsm_x4(b[nf2], sBu + (uint32_t)(((s * 128 + row) * 40 + col) * 2));
            }
            #pragma unroll
            for (int mf = 0; mf < 2; mf++)
                #pragma unroll
                for (int nf2 = 0; nf2 < 4; nf2++) {
                    mma16816(acc[mf][nf2 * 2 + 0], a[mf], b[nf2][0], b[nf2][1]);
                    mma16816(acc[mf][nf2 * 2 + 1], a[mf], b[nf2][2], b[nf2][3]);
                }
        }
    }

    const int gid = lane >> 2;
    const int tig = lane & 3;
    #pragma unroll
    for (int mf = 0; mf < 2; mf++) {
        #pragma unroll
        for (int nf = 0; nf < 8; nf++) {
            int row = m0 + wm * 32 + mf * 16 + gid;
            int col = n0 + wn * 64 + nf * 8 + tig * 2;
            float b0 = bias[col], b1 = bias[col + 1];
            float v00 = acc[mf][nf][0] + b0, v01 = acc[mf][nf][1] + b1;
            float v10 = acc[mf][nf][2] + b0, v11 = acc[mf][nf][3] + b1;
            if (mode == 3) {
                *(float2*)&out[(size_t)row * E_ + col] = make_float2(v00, v01);
                *(float2*)&out[(size_t)(row + 8) * E_ + col] = make_float2(v10, v11);
            } else {
                int h = (row >> 10) * 16 + (col >> 6);
                int t0 = row & 1023, d = col & 63;
                __nv_bfloat16 h00 = __float2bfloat16(v00), h01 = __float2bfloat16(v01);
                __nv_bfloat16 h10 = __float2bfloat16(v10), h11 = __float2bfloat16(v11);
                __nv_bfloat16 l00 = __float2bfloat16(v00 - __bfloat162float(h00));
                __nv_bfloat16 l01 = __float2bfloat16(v01 - __bfloat162float(h01));
                __nv_bfloat16 l10 = __float2bfloat16(v10 - __bfloat162float(h10));
                __nv_bfloat16 l11 = __float2bfloat16(v11 - __bfloat162float(h11));
                if (mode == 2) {
                    size_t base = ((size_t)h * 64 + d) * 1024;
                    g_vhh[base + t0] = h00;          g_vhh[base + 1024 + t0] = h01;
                    g_vhh[base + t0 + 8] = h10;      g_vhh[base + 1024 + t0 + 8] = h11;
                    g_vhl[base + t0] = l00;          g_vhl[base + 1024 + t0] = l01;
                    g_vhl[base + t0 + 8] = l10;      g_vhl[base + 1024 + t0 + 8] = l11;
                } else {
                    __nv_bfloat16* Hh = (mode == 0) ? g_qhh : g_khh;
                    __nv_bfloat16* Hl = (mode == 0) ? g_qhl : g_khl;
                    size_t i0 = ((size_t)h * 1024 + t0) * 64 + d;
                    size_t i1 = ((size_t)h * 1024 + t0 + 8) * 64 + d;
                    *(__nv_bfloat162*)(Hh + i0) = __nv_bfloat162(h00, h01);
                    *(__nv_bfloat162*)(Hl + i0) = __nv_bfloat162(l00, l01);
                    *(__nv_bfloat162*)(Hh + i1) = __nv_bfloat162(h10, h11);
                    *(__nv_bfloat162*)(Hl + i1) = __nv_bfloat162(l10, l11);
                }
            }
        }
    }
}

// ---------------------------------------------------------------------------
// Fused flash attention. Output written as hi/lo bf16 split directly into
// flat [M,E] layout in g_ahi/g_alo slot 0 (A operand of the output GEMM).
// ---------------------------------------------------------------------------
#define KSTR 72
#define VSTR 136
#define KHI_OFF 0
#define KLO_OFF 18432
#define VHI_OFF 36864
#define VLO_OFF 54272
#define STAGE_SZ 71680
#define SW_OFF  143360
#define FLASH_SMEM (SW_OFF + 1024)

__global__ void __launch_bounds__(256) flash_kernel(const float* __restrict__ weights)
{
    extern __shared__ char sm[];
    const int tid = threadIdx.x, lane = tid & 31, wid = tid >> 5;
    const int head = blockIdx.y, m0 = blockIdx.x * 128;
    const int batch = head >> 4, hidx = head & 15;
    const uint32_t smb = smem_u32(sm);

    #pragma unroll
    for (int i = 0; i < 4; i++) {
        int task = tid + i * 256;
        int r = task >> 3, ch = task & 7;
        size_t src = ((size_t)head * 1024 + m0 + r) * 64 + ch * 8;
        cp16(smb + KHI_OFF + r * 144 + ch * 16, g_qhh + src);
        cp16(smb + KLO_OFF + r * 144 + ch * 16, g_qhl + src);
    }
    CP_COMMIT();
    asm volatile("cp.async.wait_group 0;" ::: "memory");
    __syncthreads();

    uint32_t qhi[4][4], qlo[4][4];
    {
        int row = wid * 16 + (lane & 15);
        #pragma unroll
        for (int kc = 0; kc < 4; kc++) {
            int col = kc * 16 + (lane >> 4) * 8;
            ldsm_x4(qhi[kc], smb + KHI_OFF + (uint32_t)((row * KSTR + col) * 2));
            ldsm_x4(qlo[kc], smb + KLO_OFF + (uint32_t)((row * KSTR + col) * 2));
        }
    }
    __syncthreads();

    auto issue = [&](int kt, int s) {
        uint32_t base = smb + s * STAGE_SZ;
        int k0 = kt * 128;
        #pragma unroll
        for (int i = 0; i < 4; i++) {
            int task = tid + i * 256;
            int r = task >> 3, ch = task & 7;
            size_t src = ((size_t)head * 1024 + k0 + r) * 64 + ch * 8;
            cp16(base + KHI_OFF + r * 144 + ch * 16, g_khh + src);
            cp16(base + KLO_OFF + r * 144 + ch * 16, g_khl + src);
        }
        #pragma unroll
        for (int i = 0; i < 4; i++) {
            int task = tid + i * 256;
            int r = task >> 4, ch = task & 15;
            size_t src = ((size_t)head * 64 + r) * 1024 + k0 + ch * 8;
            cp16(base + VHI_OFF + r * 272 + ch * 16, g_vhh + src);
            cp16(base + VLO_OFF + r * 272 + ch * 16, g_vhl + src);
        }
        if (tid < 128) {
            float w = weights[(size_t)batch * 1024 + k0 + tid];
            float scl = (w < WEPS_) ? -1.0f : SCALE_ * w * w;
            *(float*)(sm + SW_OFF + s * 512 + tid * 4) = scl;
        }
    };

    const int gid = lane >> 2, tig = lane & 3;
    const int brow = (lane & 7) + ((lane >> 4) << 3);
    const int bcol = ((lane >> 3) & 1) * 8;

    float m_st[2] = {NEGINF_, NEGINF_};
    float l_st[2] = {0.0f, 0.0f};
    float oacc[8][4];
    #pragma unroll
    for (int i = 0; i < 8; i++)
        #pragma unroll
        for (int j = 0; j < 4; j++) oacc[i][j] = 0.0f;

    issue(0, 0);
    CP_COMMIT();

    for (int kt = 0; kt < 8; kt++) {
        const int s = kt & 1;
        if (kt + 1 < 8) {
            issue(kt + 1, s ^ 1);
            CP_COMMIT();
            asm volatile("cp.async.wait_group 1;" ::: "memory");
        } else {
            asm volatile("cp.async.wait_group 0;" ::: "memory");
        }
        __syncthreads();

        const uint32_t kb = smb + s * STAGE_SZ;
        float sacc[16][4];
        #pragma unroll
        for (int nb = 0; nb < 16; nb++)
            #pragma unroll
            for (int q = 0; q < 4; q++) sacc[nb][q] = 0.0f;

        #pragma unroll
        for (int kc = 0; kc < 4; kc++) {
            #pragma unroll
            for (int nf2 = 0; nf2 < 8; nf2++) {
                uint32_t b[4];
                int row = nf2 * 16 + brow;
                int col = kc * 16 + bcol;
                ldsm_x4(b, kb + KHI_OFF + (uint32_t)((row * KSTR + col) * 2));
                mma16816(sacc[2*nf2],   qhi[kc], b[0], b[1]);
                mma16816(sacc[2*nf2+1], qhi[kc], b[2], b[3]);
                mma16816(sacc[2*nf2],   qlo[kc], b[0], b[1]);
                mma16816(sacc[2*nf2+1], qlo[kc], b[2], b[3]);
                ldsm_x4(b, kb + KLO_OFF + (uint32_t)((row * KSTR + col) * 2));
                mma16816(sacc[2*nf2],   qhi[kc], b[0], b[1]);
                mma16816(sacc[2*nf2+1], qhi[kc], b[2], b[3]);
            }
        }

        const float* sw = (const float*)(sm + SW_OFF + s * 512);
        float mx0 = NEGINF_, mx1 = NEGINF_;
        #pragma unroll
        for (int nb = 0; nb < 16; nb++) {
            float sc0 = sw[nb * 8 + tig * 2];
            float sc1 = sw[nb * 8 + tig * 2 + 1];
            float v0 = (sc0 < 0.f) ? NEGINF_ : sacc[nb][0] * sc0;
            float v1 = (sc1 < 0.f) ? NEGINF_ : sacc[nb][1] * sc1;
            float v2 = (sc0 < 0.f) ? NEGINF_ : sacc[nb][2] * sc0;
            float v3 = (sc1 < 0.f) ? NEGINF_ : sacc[nb][3] * sc1;
            sacc[nb][0] = v0; sacc[nb][1] = v1; sacc[nb][2] = v2; sacc[nb][3] = v3;
            mx0 = fmaxf(mx0, fmaxf(v0, v1));
            mx1 = fmaxf(mx1, fmaxf(v2, v3));
        }
        mx0 = fmaxf(mx0, __shfl_xor_sync(0xffffffffu, mx0, 1));
        mx0 = fmaxf(mx0, __shfl_xor_sync(0xffffffffu, mx0, 2));
        mx1 = fmaxf(mx1, __shfl_xor_sync(0xffffffffu, mx1, 1));
        mx1 = fmaxf(mx1, __shfl_xor_sync(0xffffffffu, mx1, 2));

        float mn0 = fmaxf(m_st[0], mx0), mn1 = fmaxf(m_st[1], mx1);
        float al0 = (m_st[0] == mn0) ? 1.0f : __expf(m_st[0] - mn0);
        float al1 = (m_st[1] == mn1) ? 1.0f : __expf(m_st[1] - mn1);
        float ms0 = (mn0 <= -1e29f) ? 0.0f : mn0;
        float ms1 = (mn1 <= -1e29f) ? 0.0f : mn1;

        float sum0 = 0.f, sum1 = 0.f;
        #pragma unroll
        for (int nb = 0; nb < 16; nb++) {
            float p0 = __expf(fmaxf(sacc[nb][0] - ms0, -80.f));
            float p1 = __expf(fmaxf(sacc[nb][1] - ms0, -80.f));
            float p2 = __expf(fmaxf(sacc[nb][2] - ms1, -80.f));
            float p3 = __expf(fmaxf(sacc[nb][3] - ms1, -80.f));
            sacc[nb][0] = p0; sacc[nb][1] = p1; sacc[nb][2] = p2; sacc[nb][3] = p3;
            sum0 += p0 + p1; sum1 += p2 + p3;
        }
        sum0 += __shfl_xor_sync(0xffffffffu, sum0, 1);
        sum0 += __shfl_xor_sync(0xffffffffu, sum0, 2);
        sum1 += __shfl_xor_sync(0xffffffffu, sum1, 1);
        sum1 += __shfl_xor_sync(0xffffffffu, sum1, 2);

        l_st[0] = l_st[0] * al0 + sum0;
        l_st[1] = l_st[1] * al1 + sum1;
        m_st[0] = mn0; m_st[1] = mn1;

        #pragma unroll
        for (int nb = 0; nb < 8; nb++) {
            oacc[nb][0] *= al0; oacc[nb][1] *= al0;
            oacc[nb][2] *= al1; oacc[nb][3] *= al1;
        }

        #pragma unroll
        for (int kc = 0; kc < 8; kc++) {
            uint32_t aphi[4], aplo[4];
            #pragma unroll
            for (int half = 0; half < 2; half++) {
                float p0 = sacc[2*kc + half][0], p1 = sacc[2*kc + half][1];
                float p2 = sacc[2*kc + half][2], p3 = sacc[2*kc + half][3];
                __nv_bfloat16 h0 = __float2bfloat16(p0), h1 = __float2bfloat16(p1);
                __nv_bfloat16 h2 = __float2bfloat16(p2), h3 = __float2bfloat16(p3);
                float r0 = p0 - __bfloat162float(h0), r1 = p1 - __bfloat162float(h1);
                float r2 = p2 - __bfloat162float(h2), r3 = p3 - __bfloat162float(h3);
                __nv_bfloat162 th0(h0, h1), th1(h2, h3);
                aphi[2*half + 0] = *(uint32_t*)&th0;
                aphi[2*half + 1] = *(uint32_t*)&th1;
                aplo[2*half + 0] = pack_bf2(r0, r1);
                aplo[2*half + 1] = pack_bf2(r2, r3);
            }
            #pragma unroll
            for (int nf2 = 0; nf2 < 4; nf2++) {
                uint32_t b[4];
                int row = nf2 * 16 + brow;
                int col = kc * 16 + bcol;
                ldsm_x4(b, kb + VHI_OFF + (uint32_t)((row * VSTR + col) * 2));
                mma16816(oacc[2*nf2],   aphi, b[0], b[1]);
                mma16816(oacc[2*nf2+1], aphi, b[2], b[3]);
                mma16816(oacc[2*nf2],   aplo, b[0], b[1]);
                mma16816(oacc[2*nf2+1], aplo, b[2], b[3]);
                ldsm_x4(b, kb + VLO_OFF + (uint32_t)((row * VSTR + col) * 2));
                mma16816(oacc[2*nf2],   aphi, b[0], b[1]);
                mma16816(oacc[2*nf2+1], aphi, b[2], b[3]);
            }
        }
        __syncthreads();
    }

    // ---- normalize & write hi/lo split directly to flat [M,E] slot 0
    float inv0 = 1.0f / l_st[0], inv1 = 1.0f / l_st[1];
    int t0 = m0 + wid * 16 + gid;
    size_t mf0 = (size_t)(batch * 1024 + t0) * E_ + hidx * 64;
    size_t mf1 = mf0 + 8 * E_;
    #pragma unroll
    for (int nb = 0; nb < 8; nb++) {
        int col = nb * 8 + tig * 2;
        float v0 = oacc[nb][0] * inv0, v1 = oacc[nb][1] * inv0;
        float v2 = oacc[nb][2] * inv1, v3 = oacc[nb][3] * inv1;
        __nv_bfloat16 h0 = __float2bfloat16(v0), h1 = __float2bfloat16(v1);
        __nv_bfloat16 h2 = __float2bfloat16(v2), h3 = __float2bfloat16(v3);
        __nv_bfloat16 l0 = __float2bfloat16(v0 - __bfloat162float(h0));
        __nv_bfloat16 l1 = __float2bfloat16(v1 - __bfloat162float(h1));
        __nv_bfloat16 l2 = __float2bfloat16(v2 - __bfloat162float(h2));
        __nv_bfloat16 l3 = __float2bfloat16(v3 - __bfloat162float(h3));
        *(__nv_bfloat162*)(g_ahi + mf0 + col) = __nv_bfloat162(h0, h1);
        *(__nv_bfloat162*)(g_alo + mf0 + col) = __nv_bfloat162(l0, l1);
        *(__nv_bfloat162*)(g_ahi + mf1 + col) = __nv_bfloat162(h2, h3);
        *(__nv_bfloat162*)(g_alo + mf1 + col) = __nv_bfloat162(l2, l3);
    }
}

// ---------------------------------------------------------------------------
extern "C" void kernel_launch(void* const* d_in, const int* in_sizes, int n_in,
                              void* d_out, int out_size)
{
    const float* q       = (const float*)d_in[0];
    const float* k       = (const float*)d_in[1];
    const float* v       = (const float*)d_in[2];
    const float* weights = (const float*)d_in[3];
    const float* Wq      = (const float*)d_in[4];
    const float* bq      = (const float*)d_in[5];
    const float* Wk      = (const float*)d_in[6];
    const float* bk      = (const float*)d_in[7];
    const float* Wv      = (const float*)d_in[8];
    const float* bv      = (const float*)d_in[9];
    const float* Wo      = (const float*)d_in[10];
    const float* bo      = (const float*)d_in[11];
    float* out = (float*)d_out;

    dim3 blk(256);

    cudaFuncSetAttribute(flash_kernel, cudaFuncAttributeMaxDynamicSharedMemorySize, FLASH_SMEM);
    cudaFuncSetAttribute(gemm_mma, cudaFuncAttributeMaxDynamicSharedMemorySize, GSM_TOTAL);

    split_ws<<<(4 * EE_ / 4 + 255) / 256, blk>>>(Wq, Wk, Wv, Wo);
    split_acts<<<(3 * ME_ / 4 + 255) / 256, blk>>>(q, k, v);
    gemm_mma<<<dim3(8, 32, 3), blk, GSM_TOTAL>>>(bq, bk, bv, nullptr, 0);
    flash_kernel<<<dim3(8, 64), blk, FLASH_SMEM>>>(weights);
    gemm_mma<<<dim3(8, 32, 1), blk, GSM_TOTAL>>>(bo, bo, bo, out, 3);
}

// round 13
// speedup vs baseline: 1.6911x; 1.0834x over previous
#include <cuda_runtime.h>
#include <cuda_bf16.h>
#include <cstdint>

// ---------------- Problem constants ----------------
#define B_ 4
#define T_ 1024
#define E_ 1024
#define H_ 16
#define D_ 64
#define M_ 4096
#define SCALE_ 0.125f
#define WEPS_ 1e-5f
#define NEGINF_ -1e30f
#define LOG2E_ 1.4426950408889634f
#define ME_ (M_*E_)
#define EE_ (E_*E_)

// ---------------- Scratch (__device__ globals) ----------
__device__ __align__(16) __nv_bfloat16 g_ahi[3*ME_];   // act hi: q,k,v (slot0 reused by flash out)
__device__ __align__(16) __nv_bfloat16 g_alo[3*ME_];
__device__ __align__(16) __nv_bfloat16 g_bhi[4*EE_];   // weights hi: Wq,Wk,Wv,Wo
__device__ __align__(16) __nv_bfloat16 g_blo[4*EE_];
__device__ __align__(16) __nv_bfloat16 g_qhh[64*T_*D_];
__device__ __align__(16) __nv_bfloat16 g_qhl[64*T_*D_];
__device__ __align__(16) __nv_bfloat16 g_khh[64*T_*D_];
__device__ __align__(16) __nv_bfloat16 g_khl[64*T_*D_];
__device__ __align__(16) __nv_bfloat16 g_vhh[64*D_*T_];
__device__ __align__(16) __nv_bfloat16 g_vhl[64*D_*T_];

__device__ __forceinline__ uint32_t smem_u32(const void* p) {
    uint32_t a;
    asm("{ .reg .u64 t; cvta.to.shared.u64 t, %1; cvt.u32.u64 %0, t; }" : "=r"(a) : "l"(p));
    return a;
}
__device__ __forceinline__ void cp16(uint32_t dst, const void* src) {
    asm volatile("cp.async.ca.shared.global [%0], [%1], 16;" :: "r"(dst), "l"(src));
}
#define CP_COMMIT() asm volatile("cp.async.commit_group;" ::: "memory")

__device__ __forceinline__ void ldsm_x4(uint32_t* r, uint32_t addr) {
    asm volatile("ldmatrix.sync.aligned.m8n8.x4.shared.b16 {%0,%1,%2,%3}, [%4];"
        : "=r"(r[0]), "=r"(r[1]), "=r"(r[2]), "=r"(r[3]) : "r"(addr));
}
__device__ __forceinline__ void mma16816(float* c, const uint32_t* a, uint32_t b0, uint32_t b1) {
    asm volatile("mma.sync.aligned.m16n8k16.row.col.f32.bf16.bf16.f32 "
        "{%0,%1,%2,%3}, {%4,%5,%6,%7}, {%8,%9}, {%0,%1,%2,%3};"
        : "+f"(c[0]), "+f"(c[1]), "+f"(c[2]), "+f"(c[3])
        : "r"(a[0]), "r"(a[1]), "r"(a[2]), "r"(a[3]), "r"(b0), "r"(b1));
}
__device__ __forceinline__ float ex2f(float x) {
    float y; asm("ex2.approx.f32 %0, %1;" : "=f"(y) : "f"(x)); return y;
}

// ---------------------------------------------------------------------------
// One fused split kernel: q,k,v -> g_ahi/g_alo slots; Wq..Wo -> g_bhi/g_blo.
// ---------------------------------------------------------------------------
#define ACT4 (ME_/4)
#define W4   (EE_/4)

__global__ void split_all(const float* __restrict__ q, const float* __restrict__ k,
                          const float* __restrict__ v, const float* __restrict__ w0,
                          const float* __restrict__ w1, const float* __restrict__ w2,
                          const float* __restrict__ w3)
{
    int i = blockIdx.x * blockDim.x + threadIdx.x;
    const float* src;
    __nv_bfloat16 *dh, *dl;
    size_t o2;
    if (i < 3 * ACT4) {
        int slot = i / ACT4, off = i - slot * ACT4;
        src = (slot == 0) ? q : (slot == 1) ? k : v;
        o2 = ((size_t)slot * ME_ + (size_t)off * 4) >> 1;
        dh = g_ahi; dl = g_alo;
        src += (size_t)off * 4 - (size_t)off * 4;          // no-op, keep src base
        src = ((const float*)src) ;
        float4 x = ((const float4*)src)[off];
        __nv_bfloat16 h0 = __float2bfloat16(x.x), h1 = __float2bfloat16(x.y);
        __nv_bfloat16 h2 = __float2bfloat16(x.z), h3 = __float2bfloat16(x.w);
        __nv_bfloat16 l0 = __float2bfloat16(x.x - __bfloat162float(h0));
        __nv_bfloat16 l1 = __float2bfloat16(x.y - __bfloat162float(h1));
        __nv_bfloat16 l2 = __float2bfloat16(x.z - __bfloat162float(h2));
        __nv_bfloat16 l3 = __float2bfloat16(x.w - __bfloat162float(h3));
        ((__nv_bfloat162*)dh)[o2+0] = __nv_bfloat162(h0, h1);
        ((__nv_bfloat162*)dh)[o2+1] = __nv_bfloat162(h2, h3);
        ((__nv_bfloat162*)dl)[o2+0] = __nv_bfloat162(l0, l1);
        ((__nv_bfloat162*)dl)[o2+1] = __nv_bfloat162(l2, l3);
    } else {
        int j = i - 3 * ACT4;
        if (j >= 4 * W4) return;
        int slot = j / W4, off = j - slot * W4;
        src = (slot == 0) ? w0 : (slot == 1) ? w1 : (slot == 2) ? w2 : w3;
        o2 = ((size_t)slot * EE_ + (size_t)off * 4) >> 1;
        float4 x = ((const float4*)src)[off];
        __nv_bfloat16 h0 = __float2bfloat16(x.x), h1 = __float2bfloat16(x.y);
        __nv_bfloat16 h2 = __float2bfloat16(x.z), h3 = __float2bfloat16(x.w);
        __nv_bfloat16 l0 = __float2bfloat16(x.x - __bfloat162float(h0));
        __nv_bfloat16 l1 = __float2bfloat16(x.y - __bfloat162float(h1));
        __nv_bfloat16 l2 = __float2bfloat16(x.z - __bfloat162float(h2));
        __nv_bfloat16 l3 = __float2bfloat16(x.w - __bfloat162float(h3));
        ((__nv_bfloat162*)g_bhi)[o2+0] = __nv_bfloat162(h0, h1);
        ((__nv_bfloat162*)g_bhi)[o2+1] = __nv_bfloat162(h2, h3);
        ((__nv_bfloat162*)g_blo)[o2+0] = __nv_bfloat162(l0, l1);
        ((__nv_bfloat162*)g_blo)[o2+1] = __nv_bfloat162(l2, l3);
    }
}

// ---------------------------------------------------------------------------
// HMMA GEMM, K-chunk 64, 4-stage cp.async pipeline (144 KB smem), 1 CTA/SM.
// C = A·B^T over K'=3072 (hi/lo 3-term). CTA 128x128, 8 warps.
// base_mode 0: mode=blockIdx.z (0=Q,1=K,2=V); base_mode 3: fp32 out + bias.
// smem stride 72 bf16/row (36 words mod 32 = +4 -> conflict-free LDSM).
// ---------------------------------------------------------------------------
#define GSTR 72
#define GSTAGE 18432                 // 128*72*2 bytes per operand per stage
#define GA_SZ (4*GSTAGE)             // 73728
#define GSM_TOTAL (8*GSTAGE)         // 147456
#define NCHUNK 48

__global__ void __launch_bounds__(256) gemm_mma(
    const float* __restrict__ bias0, const float* __restrict__ bias1,
    const float* __restrict__ bias2, float* __restrict__ out, int base_mode)
{
    extern __shared__ char gsm[];
    const int tid = threadIdx.x;
    const int lane = tid & 31;
    const int wid = tid >> 5;
    const int wm = wid & 3;
    const int wn = wid >> 2;
    const int m0 = blockIdx.y * 128;
    const int n0 = blockIdx.x * 128;
    const int mode = (base_mode == 3) ? 3 : (int)blockIdx.z;
    const int aslot = (mode == 3) ? 0 : mode;
    const int wslot = (mode == 3) ? 3 : mode;
    const float* bias = (mode == 1) ? bias1 : (mode == 2) ? bias2 : bias0;

    const __nv_bfloat16* Ahi = g_ahi + (size_t)aslot * ME_;
    const __nv_bfloat16* Alo = g_alo + (size_t)aslot * ME_;
    const __nv_bfloat16* Bhi = g_bhi + (size_t)wslot * EE_;
    const __nv_bfloat16* Blo = g_blo + (size_t)wslot * EE_;

    const uint32_t sAu = smem_u32(gsm);
    const uint32_t sBu = sAu + GA_SZ;

    float acc[2][8][4];
    #pragma unroll
    for (int i = 0; i < 2; i++)
        #pragma unroll
        for (int j = 0; j < 8; j++)
            #pragma unroll
            for (int q = 0; q < 4; q++) acc[i][j][q] = 0.0f;

    auto issue = [&](int c, int s) {
        const __nv_bfloat16* Ap = (c < 16 || c >= 32) ? Ahi : Alo;
        const __nv_bfloat16* Bp = (c < 32) ? Bhi : Blo;
        const int koff = (c & 15) * 64;
        #pragma unroll
        for (int i = 0; i < 4; i++) {
            int f = tid + i * 256;              // 0..1023
            int row = f >> 3, ch = f & 7;       // 128 rows x 8 col-groups
            uint32_t off = (uint32_t)(((s * 128 + row) * GSTR + ch * 8) * 2);
            cp16(sAu + off, Ap + (size_t)(m0 + row) * E_ + koff + ch * 8);
            cp16(sBu + off, Bp + (size_t)(n0 + row) * E_ + koff + ch * 8);
        }
    };

    issue(0, 0); CP_COMMIT();
    issue(1, 1); CP_COMMIT();
    issue(2, 2); CP_COMMIT();

    for (int c = 0; c < NCHUNK; c++) {
        const int s = c & 3;
        if (c <= NCHUNK - 3)      asm volatile("cp.async.wait_group 2;" ::: "memory");
        else if (c == NCHUNK - 2) asm volatile("cp.async.wait_group 1;" ::: "memory");
        else                      asm volatile("cp.async.wait_group 0;" ::: "memory");
        __syncthreads();
        if (c + 3 < NCHUNK) { issue(c + 3, (c + 3) & 3); CP_COMMIT(); }

        #pragma unroll
        for (int ks = 0; ks < 4; ks++) {
            uint32_t a[2][4];
            #pragma unroll
            for (int mf = 0; mf < 2; mf++) {
                int row = wm * 32 + mf * 16 + (lane & 15);
                int col = ks * 16 + (lane >> 4) * 8;
                ldsm_x4(a[mf], sAu + (uint32_t)(((s * 128 + row) * GSTR + col) * 2));
            }
            uint32_t b[4][4];
            #pragma unroll
            for (int nf2 = 0; nf2 < 4; nf2++) {
                int row = wn * 64 + nf2 * 16 + (lane & 7) + (lane >> 4) * 8;
                int col = ks * 16 + ((lane >> 3) & 1) * 8;
                ldsm_x4(b[nf2], sBu + (uint32_t)(((s * 128 + row) * GSTR + col) * 2));
            }
            #pragma unroll
            for (int mf = 0; mf < 2; mf++)
                #pragma unroll
                for (int nf2 = 0; nf2 < 4; nf2++) {
                    mma16816(acc[mf][nf2 * 2 + 0], a[mf], b[nf2][0], b[nf2][1]);
                    mma16816(acc[mf][nf2 * 2 + 1], a[mf], b[nf2][2], b[nf2][3]);
                }
        }
    }

    const int gid = lane >> 2;
    const int tig = lane & 3;
    #pragma unroll
    for (int mf = 0; mf < 2; mf++) {
        #pragma unroll
        for (int nf = 0; nf < 8; nf++) {
            int row = m0 + wm * 32 + mf * 16 + gid;
            int col = n0 + wn * 64 + nf * 8 + tig * 2;
            float b0 = bias[col], b1 = bias[col + 1];
            float v00 = acc[mf][nf][0] + b0, v01 = acc[mf][nf][1] + b1;
            float v10 = acc[mf][nf][2] + b0, v11 = acc[mf][nf][3] + b1;
            if (mode == 3) {
                *(float2*)&out[(size_t)row * E_ + col] = make_float2(v00, v01);
                *(float2*)&out[(size_t)(row + 8) * E_ + col] = make_float2(v10, v11);
            } else {
                int h = (row >> 10) * 16 + (col >> 6);
                int t0 = row & 1023, d = col & 63;
                __nv_bfloat16 h00 = __float2bfloat16(v00), h01 = __float2bfloat16(v01);
                __nv_bfloat16 h10 = __float2bfloat16(v10), h11 = __float2bfloat16(v11);
                __nv_bfloat16 l00 = __float2bfloat16(v00 - __bfloat162float(h00));
                __nv_bfloat16 l01 = __float2bfloat16(v01 - __bfloat162float(h01));
                __nv_bfloat16 l10 = __float2bfloat16(v10 - __bfloat162float(h10));
                __nv_bfloat16 l11 = __float2bfloat16(v11 - __bfloat162float(h11));
                if (mode == 2) {
                    size_t base = ((size_t)h * 64 + d) * 1024;
                    g_vhh[base + t0] = h00;          g_vhh[base + 1024 + t0] = h01;
                    g_vhh[base + t0 + 8] = h10;      g_vhh[base + 1024 + t0 + 8] = h11;
                    g_vhl[base + t0] = l00;          g_vhl[base + 1024 + t0] = l01;
                    g_vhl[base + t0 + 8] = l10;      g_vhl[base + 1024 + t0 + 8] = l11;
                } else {
                    __nv_bfloat16* Hh = (mode == 0) ? g_qhh : g_khh;
                    __nv_bfloat16* Hl = (mode == 0) ? g_qhl : g_khl;
                    size_t i0 = ((size_t)h * 1024 + t0) * 64 + d;
                    size_t i1 = ((size_t)h * 1024 + t0 + 8) * 64 + d;
                    *(__nv_bfloat162*)(Hh + i0) = __nv_bfloat162(h00, h01);
                    *(__nv_bfloat162*)(Hl + i0) = __nv_bfloat162(l00, l01);
                    *(__nv_bfloat162*)(Hh + i1) = __nv_bfloat162(h10, h11);
                    *(__nv_bfloat162*)(Hl + i1) = __nv_bfloat162(l10, l11);
                }
            }
        }
    }
}

// ---------------------------------------------------------------------------
// Fused flash attention (exp2 softmax domain, truncation hi/lo P packing).
// Output written hi/lo bf16 to flat [M,E] slot 0 of g_ahi/g_alo.
// ---------------------------------------------------------------------------
#define KSTR 72
#define VSTR 136
#define KHI_OFF 0
#define KLO_OFF 18432
#define VHI_OFF 36864
#define VLO_OFF 54272
#define STAGE_SZ 71680
#define SW_OFF  143360
#define FLASH_SMEM (SW_OFF + 1024)

__global__ void __launch_bounds__(256) flash_kernel(const float* __restrict__ weights)
{
    extern __shared__ char sm[];
    const int tid = threadIdx.x, lane = tid & 31, wid = tid >> 5;
    const int head = blockIdx.y, m0 = blockIdx.x * 128;
    const int batch = head >> 4, hidx = head & 15;
    const uint32_t smb = smem_u32(sm);

    #pragma unroll
    for (int i = 0; i < 4; i++) {
        int task = tid + i * 256;
        int r = task >> 3, ch = task & 7;
        size_t src = ((size_t)head * 1024 + m0 + r) * 64 + ch * 8;
        cp16(smb + KHI_OFF + r * 144 + ch * 16, g_qhh + src);
        cp16(smb + KLO_OFF + r * 144 + ch * 16, g_qhl + src);
    }
    CP_COMMIT();
    asm volatile("cp.async.wait_group 0;" ::: "memory");
    __syncthreads();

    uint32_t qhi[4][4], qlo[4][4];
    {
        int row = wid * 16 + (lane & 15);
        #pragma unroll
        for (int kc = 0; kc < 4; kc++) {
            int col = kc * 16 + (lane >> 4) * 8;
            ldsm_x4(qhi[kc], smb + KHI_OFF + (uint32_t)((row * KSTR + col) * 2));
            ldsm_x4(qlo[kc], smb + KLO_OFF + (uint32_t)((row * KSTR + col) * 2));
        }
    }
    __syncthreads();

    auto issue = [&](int kt, int s) {
        uint32_t base = smb + s * STAGE_SZ;
        int k0 = kt * 128;
        #pragma unroll
        for (int i = 0; i < 4; i++) {
            int task = tid + i * 256;
            int r = task >> 3, ch = task & 7;
            size_t src = ((size_t)head * 1024 + k0 + r) * 64 + ch * 8;
            cp16(base + KHI_OFF + r * 144 + ch * 16, g_khh + src);
            cp16(base + KLO_OFF + r * 144 + ch * 16, g_khl + src);
        }
        #pragma unroll
        for (int i = 0; i < 4; i++) {
            int task = tid + i * 256;
            int r = task >> 4, ch = task & 15;
            size_t src = ((size_t)head * 64 + r) * 1024 + k0 + ch * 8;
            cp16(base + VHI_OFF + r * 272 + ch * 16, g_vhh + src);
            cp16(base + VLO_OFF + r * 272 + ch * 16, g_vhl + src);
        }
        if (tid < 128) {
            float w = weights[(size_t)batch * 1024 + k0 + tid];
            float scl = (w < WEPS_) ? -1.0f : SCALE_ * w * w * LOG2E_;   // log2 domain
            *(float*)(sm + SW_OFF + s * 512 + tid * 4) = scl;
        }
    };

    const int gid = lane >> 2, tig = lane & 3;
    const int brow = (lane & 7) + ((lane >> 4) << 3);
    const int bcol = ((lane >> 3) & 1) * 8;

    float m_st[2] = {NEGINF_, NEGINF_};
    float l_st[2] = {0.0f, 0.0f};
    float oacc[8][4];
    #pragma unroll
    for (int i = 0; i < 8; i++)
        #pragma unroll
        for (int j = 0; j < 4; j++) oacc[i][j] = 0.0f;

    issue(0, 0);
    CP_COMMIT();

    for (int kt = 0; kt < 8; kt++) {
        const int s = kt & 1;
        if (kt + 1 < 8) {
            issue(kt + 1, s ^ 1);
            CP_COMMIT();
            asm volatile("cp.async.wait_group 1;" ::: "memory");
        } else {
            asm volatile("cp.async.wait_group 0;" ::: "memory");
        }
        __syncthreads();

        const uint32_t kb = smb + s * STAGE_SZ;
        float sacc[16][4];
        #pragma unroll
        for (int nb = 0; nb < 16; nb++)
            #pragma unroll
            for (int q = 0; q < 4; q++) sacc[nb][q] = 0.0f;

        #pragma unroll
        for (int kc = 0; kc < 4; kc++) {
            #pragma unroll
            for (int nf2 = 0; nf2 < 8; nf2++) {
                uint32_t b[4];
                int row = nf2 * 16 + brow;
                int col = kc * 16 + bcol;
                ldsm_x4(b, kb + KHI_OFF + (uint32_t)((row * KSTR + col) * 2));
                mma16816(sacc[2*nf2],   qhi[kc], b[0], b[1]);
                mma16816(sacc[2*nf2+1], qhi[kc], b[2], b[3]);
                mma16816(sacc[2*nf2],   qlo[kc], b[0], b[1]);
                mma16816(sacc[2*nf2+1], qlo[kc], b[2], b[3]);
                ldsm_x4(b, kb + KLO_OFF + (uint32_t)((row * KSTR + col) * 2));
                mma16816(sacc[2*nf2],   qhi[kc], b[0], b[1]);
                mma16816(sacc[2*nf2+1], qhi[kc], b[2], b[3]);
            }
        }

        const float* sw = (const float*)(sm + SW_OFF + s * 512);
        float mx0 = NEGINF_, mx1 = NEGINF_;
        #pragma unroll
        for (int nb = 0; nb < 16; nb++) {
            float sc0 = sw[nb * 8 + tig * 2];
            float sc1 = sw[nb * 8 + tig * 2 + 1];
            float v0 = (sc0 < 0.f) ? NEGINF_ : sacc[nb][0] * sc0;
            float v1 = (sc1 < 0.f) ? NEGINF_ : sacc[nb][1] * sc1;
            float v2 = (sc0 < 0.f) ? NEGINF_ : sacc[nb][2] * sc0;
            float v3 = (sc1 < 0.f) ? NEGINF_ : sacc[nb][3] * sc1;
            sacc[nb][0] = v0; sacc[nb][1] = v1; sacc[nb][2] = v2; sacc[nb][3] = v3;
            mx0 = fmaxf(mx0, fmaxf(v0, v1));
            mx1 = fmaxf(mx1, fmaxf(v2, v3));
        }
        mx0 = fmaxf(mx0, __shfl_xor_sync(0xffffffffu, mx0, 1));
        mx0 = fmaxf(mx0, __shfl_xor_sync(0xffffffffu, mx0, 2));
        mx1 = fmaxf(mx1, __shfl_xor_sync(0xffffffffu, mx1, 1));
        mx1 = fmaxf(mx1, __shfl_xor_sync(0xffffffffu, mx1, 2));

        float mn0 = fmaxf(m_st[0], mx0), mn1 = fmaxf(m_st[1], mx1);
        float al0 = ex2f(m_st[0] - mn0);      // 0 if first real tile, 1 if unchanged
        float al1 = ex2f(m_st[1] - mn1);
        float ms0 = (mn0 <= -1e29f) ? 0.0f : mn0;
        float ms1 = (mn1 <= -1e29f) ? 0.0f : mn1;

        float sum0 = 0.f, sum1 = 0.f;
        #pragma unroll
        for (int nb = 0; nb < 16; nb++) {
            float p0 = ex2f(sacc[nb][0] - ms0);
            float p1 = ex2f(sacc[nb][1] - ms0);
            float p2 = ex2f(sacc[nb][2] - ms1);
            float p3 = ex2f(sacc[nb][3] - ms1);
            sacc[nb][0] = p0; sacc[nb][1] = p1; sacc[nb][2] = p2; sacc[nb][3] = p3;
            sum0 += p0 + p1; sum1 += p2 + p3;
        }
        sum0 += __shfl_xor_sync(0xffffffffu, sum0, 1);
        sum0 += __shfl_xor_sync(0xffffffffu, sum0, 2);
        sum1 += __shfl_xor_sync(0xffffffffu, sum1, 1);
        sum1 += __shfl_xor_sync(0xffffffffu, sum1, 2);

        l_st[0] = l_st[0] * al0 + sum0;
        l_st[1] = l_st[1] * al1 + sum1;
        m_st[0] = mn0; m_st[1] = mn1;

        #pragma unroll
        for (int nb = 0; nb < 8; nb++) {
            oacc[nb][0] *= al0; oacc[nb][1] *= al0;
            oacc[nb][2] *= al1; oacc[nb][3] *= al1;
        }

        #pragma unroll
        for (int kc = 0; kc < 8; kc++) {
            uint32_t aphi[4], aplo[4];
            #pragma unroll
            for (int half = 0; half < 2; half++) {
                float p0 = sacc[2*kc + half][0], p1 = sacc[2*kc + half][1];
                float p2 = sacc[2*kc + half][2], p3 = sacc[2*kc + half][3];
                // truncation split: hi = top 16 bits; lo = exact residual, bf16-rounded
                uint32_t u0 = __float_as_uint(p0) & 0xffff0000u;
                uint32_t u1 = __float_as_uint(p1) & 0xffff0000u;
                uint32_t u2 = __float_as_uint(p2) & 0xffff0000u;
                uint32_t u3 = __float_as_uint(p3) & 0xffff0000u;
                float r0 = p0 - __uint_as_float(u0);
                float r1 = p1 - __uint_as_float(u1);
                float r2 = p2 - __uint_as_float(u2);
                float r3 = p3 - __uint_as_float(u3);
                uint32_t hi01, hi23, lo01, lo23;
                asm("prmt.b32 %0, %1, %2, 0x7632;" : "=r"(hi01) : "r"(u0), "r"(u1));
                asm("prmt.b32 %0, %1, %2, 0x7632;" : "=r"(hi23) : "r"(u2), "r"(u3));
                asm("cvt.rn.bf16x2.f32 %0, %1, %2;" : "=r"(lo01) : "f"(r1), "f"(r0));
                asm("cvt.rn.bf16x2.f32 %0, %1, %2;" : "=r"(lo23) : "f"(r3), "f"(r2));
                aphi[2*half + 0] = hi01; aphi[2*half + 1] = hi23;
                aplo[2*half + 0] = lo01; aplo[2*half + 1] = lo23;
            }
            #pragma unroll
            for (int nf2 = 0; nf2 < 4; nf2++) {
                uint32_t b[4];
                int row = nf2 * 16 + brow;
                int col = kc * 16 + bcol;
                ldsm_x4(b, kb + VHI_OFF + (uint32_t)((row * VSTR + col) * 2));
                mma16816(oacc[2*nf2],   aphi, b[0], b[1]);
                mma16816(oacc[2*nf2+1], aphi, b[2], b[3]);
                mma16816(oacc[2*nf2],   aplo, b[0], b[1]);
                mma16816(oacc[2*nf2+1], aplo, b[2], b[3]);
                ldsm_x4(b, kb + VLO_OFF + (uint32_t)((row * VSTR + col) * 2));
                mma16816(oacc[2*nf2],   aphi, b[0], b[1]);
                mma16816(oacc[2*nf2+1], aphi, b[2], b[3]);
            }
        }
        __syncthreads();
    }

    float inv0 = 1.0f / l_st[0], inv1 = 1.0f / l_st[1];
    int t0 = m0 + wid * 16 + gid;
    size_t mf0 = (size_t)(batch * 1024 + t0) * E_ + hidx * 64;
    size_t mf1 = mf0 + 8 * E_;
    #pragma unroll
    for (int nb = 0; nb < 8; nb++) {
        int col = nb * 8 + tig * 2;
        float v0 = oacc[nb][0] * inv0, v1 = oacc[nb][1] * inv0;
        float v2 = oacc[nb][2] * inv1, v3 = oacc[nb][3] * inv1;
        __nv_bfloat16 h0 = __float2bfloat16(v0), h1 = __float2bfloat16(v1);
        __nv_bfloat16 h2 = __float2bfloat16(v2), h3 = __float2bfloat16(v3);
        __nv_bfloat16 l0 = __float2bfloat16(v0 - __bfloat162float(h0));
        __nv_bfloat16 l1 = __float2bfloat16(v1 - __bfloat162float(h1));
        __nv_bfloat16 l2 = __float2bfloat16(v2 - __bfloat162float(h2));
        __nv_bfloat16 l3 = __float2bfloat16(v3 - __bfloat162float(h3));
        *(__nv_bfloat162*)(g_ahi + mf0 + col) = __nv_bfloat162(h0, h1);
        *(__nv_bfloat162*)(g_alo + mf0 + col) = __nv_bfloat162(l0, l1);
        *(__nv_bfloat162*)(g_ahi + mf1 + col) = __nv_bfloat162(h2, h3);
        *(__nv_bfloat162*)(g_alo + mf1 + col) = __nv_bfloat162(l2, l3);
    }
}

// ---------------------------------------------------------------------------
extern "C" void kernel_launch(void* const* d_in, const int* in_sizes, int n_in,
                              void* d_out, int out_size)
{
    const float* q       = (const float*)d_in[0];
    const float* k       = (const float*)d_in[1];
    const float* v       = (const float*)d_in[2];
    const float* weights = (const float*)d_in[3];
    const float* Wq      = (const float*)d_in[4];
    const float* bq      = (const float*)d_in[5];
    const float* Wk      = (const float*)d_in[6];
    const float* bk      = (const float*)d_in[7];
    const float* Wv      = (const float*)d_in[8];
    const float* bv      = (const float*)d_in[9];
    const float* Wo      = (const float*)d_in[10];
    const float* bo      = (const float*)d_in[11];
    float* out = (float*)d_out;

    dim3 blk(256);

    cudaFuncSetAttribute(flash_kernel, cudaFuncAttributeMaxDynamicSharedMemorySize, FLASH_SMEM);
    cudaFuncSetAttribute(gemm_mma, cudaFuncAttributeMaxDynamicSharedMemorySize, GSM_TOTAL);

    int total4 = 3 * ACT4 + 4 * W4;
    split_all<<<(total4 + 255) / 256, blk>>>(q, k, v, Wq, Wk, Wv, Wo);
    gemm_mma<<<dim3(8, 32, 3), blk, GSM_TOTAL>>>(bq, bk, bv, nullptr, 0);
    flash_kernel<<<dim3(8, 64), blk, FLASH_SMEM>>>(weights);
    gemm_mma<<<dim3(8, 32, 1), blk, GSM_TOTAL>>>(bo, bo, bo, out, 3);
}